// round 2
// baseline (speedup 1.0000x reference)
#include <cuda_runtime.h>
#include <math.h>

// Problem constants
#define B_ 4
#define C_ 2048
#define H_ 24
#define W_ 24
#define L_ 576            // H_*W_
#define K2C_ 4096         // 2*C_

// ---------------- scratch (device globals; no allocation allowed) ----------------
__device__ float g_xt_ref[B_ * L_ * C_];   // part_ref transposed   [b][l][c]
__device__ float g_xt_tgt[B_ * L_ * C_];   // part_target transposed [b][l][c]
__device__ float g_q[B_ * L_ * C_];        // q = Wq x_tgt + bq     [b][l][c]
__device__ float g_k[B_ * L_ * C_];        // k = Wk x_ref + bk     [b][l][c]
__device__ float g_G[B_ * L_ * L_];        // pixel Gram k·q        [b][l][m]
__device__ float g_nq[B_ * L_];            // per-pixel sq norm of q
__device__ float g_nk[B_ * L_];            // per-pixel sq norm of k
__device__ float g_inq[B_ * L_];           // 1/max(sqrt(patch-sum nq), eps)
__device__ float g_ink[B_ * L_];
__device__ float g_S[B_ * L_];             // R_star
__device__ int   g_arg[B_ * L_];           // argmax l per m
__device__ int   g_src[B_ * L_ * 9];       // gather source rows (or -1)
__device__ float g_T[B_ * L_ * C_];        // T_part               [b][y][c]

// ---------------- transpose [b][c][l] -> [b][l][c] ----------------
__global__ void transpose_cl_lc(const float* __restrict__ in, float* __restrict__ out) {
    __shared__ float t[32][33];
    int b = blockIdx.z;
    int l0 = blockIdx.x * 32, c0 = blockIdx.y * 32;
    const float* inb = in + (size_t)b * C_ * L_;
    float* outb = out + (size_t)b * L_ * C_;
    int tx = threadIdx.x, ty = threadIdx.y;
#pragma unroll
    for (int j = 0; j < 32; j += 8)
        t[ty + j][tx] = inb[(size_t)(c0 + ty + j) * L_ + (l0 + tx)];
    __syncthreads();
#pragma unroll
    for (int j = 0; j < 32; j += 8)
        outb[(size_t)(l0 + ty + j) * C_ + (c0 + tx)] = t[tx][ty + j];
}

// ---------------- tiling params ----------------
#define BM 128
#define BN 128
#define BKK 16
#define TM 8
#define TN 8

// =====================================================================
// Double-buffered NT GEMM core (A[m][k], B[n][k] row-major K-fastest).
// Each thread loads 1 float4 of A-tile and 1 float4 of B-tile per K-step.
// One __syncthreads per mainloop iteration.
// =====================================================================

// ---- fused q/k projection: z<B -> q=Wq*xt_tgt+bq ; z>=B -> k=Wk*xt_ref+bk
__global__ __launch_bounds__(256, 2)
void gemm_qk(const float* __restrict__ XT_tgt, const float* __restrict__ XT_ref,
             const float* __restrict__ Wq, const float* __restrict__ Bq,
             const float* __restrict__ Wk, const float* __restrict__ Bk,
             float* __restrict__ Qo, float* __restrict__ Ko) {
    __shared__ float As[2][BKK][BM + 4];
    __shared__ float Bs[2][BKK][BN + 4];
    int z = blockIdx.z;
    int b = z & 3;
    bool isQ = z < B_;
    const float* A = (isQ ? XT_tgt : XT_ref) + (size_t)b * L_ * C_;  // [L][C]
    const float* Wm = isQ ? Wq : Wk;                                  // [C][C]
    const float* bias = isQ ? Bq : Bk;
    float* Out = (isQ ? Qo : Ko) + (size_t)b * L_ * C_;               // [L][C]
    const int M = L_, N = C_, K = C_;

    int m0 = blockIdx.y * BM, n0 = blockIdx.x * BN;
    int tid = threadIdx.x;
    int tx = tid & 15, ty = tid >> 4;
    int lr = tid >> 2;           // 0..63
    int lk = (tid & 3) * 4;      // 0,4,8,12
    float acc[TM][TN];
#pragma unroll
    for (int i = 0; i < TM; i++)
#pragma unroll
        for (int j = 0; j < TN; j++) acc[i][j] = 0.f;

    // preload tile 0
    float4 ra[2], rb[2];
#pragma unroll
    for (int p = 0; p < 2; p++) {
        int row = lr + p * 64;
        ra[p] = make_float4(0.f, 0.f, 0.f, 0.f);
        if (m0 + row < M) ra[p] = *(const float4*)(A + (size_t)(m0 + row) * K + lk);
        rb[p] = *(const float4*)(Wm + (size_t)(n0 + row) * K + lk);
    }
    int cur = 0;
#pragma unroll
    for (int p = 0; p < 2; p++) {
        int row = lr + p * 64;
        As[0][lk + 0][row] = ra[p].x; As[0][lk + 1][row] = ra[p].y;
        As[0][lk + 2][row] = ra[p].z; As[0][lk + 3][row] = ra[p].w;
        Bs[0][lk + 0][row] = rb[p].x; Bs[0][lk + 1][row] = rb[p].y;
        Bs[0][lk + 2][row] = rb[p].z; Bs[0][lk + 3][row] = rb[p].w;
    }
    __syncthreads();

    for (int k0 = BKK; k0 <= K; k0 += BKK) {
        bool haveNext = (k0 < K);
        if (haveNext) {
#pragma unroll
            for (int p = 0; p < 2; p++) {
                int row = lr + p * 64;
                ra[p] = make_float4(0.f, 0.f, 0.f, 0.f);
                if (m0 + row < M) ra[p] = *(const float4*)(A + (size_t)(m0 + row) * K + k0 + lk);
                rb[p] = *(const float4*)(Wm + (size_t)(n0 + row) * K + k0 + lk);
            }
        }
#pragma unroll
        for (int kk = 0; kk < BKK; kk++) {
            float af[TM], bf[TN];
#pragma unroll
            for (int i = 0; i < TM; i++) af[i] = As[cur][kk][ty * TM + i];
#pragma unroll
            for (int j = 0; j < TN; j++) bf[j] = Bs[cur][kk][tx * TN + j];
#pragma unroll
            for (int i = 0; i < TM; i++)
#pragma unroll
                for (int j = 0; j < TN; j++) acc[i][j] += af[i] * bf[j];
        }
        if (haveNext) {
            int nxt = cur ^ 1;
#pragma unroll
            for (int p = 0; p < 2; p++) {
                int row = lr + p * 64;
                As[nxt][lk + 0][row] = ra[p].x; As[nxt][lk + 1][row] = ra[p].y;
                As[nxt][lk + 2][row] = ra[p].z; As[nxt][lk + 3][row] = ra[p].w;
                Bs[nxt][lk + 0][row] = rb[p].x; Bs[nxt][lk + 1][row] = rb[p].y;
                Bs[nxt][lk + 2][row] = rb[p].z; Bs[nxt][lk + 3][row] = rb[p].w;
            }
            __syncthreads();
            cur = nxt;
        }
    }
#pragma unroll
    for (int i = 0; i < TM; i++) {
        int m = m0 + ty * TM + i;
        if (m >= M) continue;
#pragma unroll
        for (int j = 0; j < TN; j++) {
            int n = n0 + tx * TN + j;
            Out[(size_t)m * N + n] = acc[i][j] + bias[n];
        }
    }
}

// ---- Gram GEMM: G[b][l][m] = sum_c k[b][l][c] * q[b][m][c]   (M=N=L, K=C)
__global__ __launch_bounds__(256, 2)
void gemm_gram(const float* __restrict__ Kt, const float* __restrict__ Qt,
               float* __restrict__ G) {
    __shared__ float As[2][BKK][BM + 4];
    __shared__ float Bs[2][BKK][BN + 4];
    int b = blockIdx.z;
    const float* A = Kt + (size_t)b * L_ * C_;
    const float* Bm = Qt + (size_t)b * L_ * C_;
    float* Out = G + (size_t)b * L_ * L_;
    const int M = L_, N = L_, K = C_;

    int m0 = blockIdx.y * BM, n0 = blockIdx.x * BN;
    int tid = threadIdx.x;
    int tx = tid & 15, ty = tid >> 4;
    int lr = tid >> 2;
    int lk = (tid & 3) * 4;
    float acc[TM][TN];
#pragma unroll
    for (int i = 0; i < TM; i++)
#pragma unroll
        for (int j = 0; j < TN; j++) acc[i][j] = 0.f;

    float4 ra[2], rb[2];
#pragma unroll
    for (int p = 0; p < 2; p++) {
        int row = lr + p * 64;
        ra[p] = make_float4(0.f, 0.f, 0.f, 0.f);
        rb[p] = ra[p];
        if (m0 + row < M) ra[p] = *(const float4*)(A + (size_t)(m0 + row) * K + lk);
        if (n0 + row < N) rb[p] = *(const float4*)(Bm + (size_t)(n0 + row) * K + lk);
    }
    int cur = 0;
#pragma unroll
    for (int p = 0; p < 2; p++) {
        int row = lr + p * 64;
        As[0][lk + 0][row] = ra[p].x; As[0][lk + 1][row] = ra[p].y;
        As[0][lk + 2][row] = ra[p].z; As[0][lk + 3][row] = ra[p].w;
        Bs[0][lk + 0][row] = rb[p].x; Bs[0][lk + 1][row] = rb[p].y;
        Bs[0][lk + 2][row] = rb[p].z; Bs[0][lk + 3][row] = rb[p].w;
    }
    __syncthreads();

    for (int k0 = BKK; k0 <= K; k0 += BKK) {
        bool haveNext = (k0 < K);
        if (haveNext) {
#pragma unroll
            for (int p = 0; p < 2; p++) {
                int row = lr + p * 64;
                ra[p] = make_float4(0.f, 0.f, 0.f, 0.f);
                rb[p] = ra[p];
                if (m0 + row < M) ra[p] = *(const float4*)(A + (size_t)(m0 + row) * K + k0 + lk);
                if (n0 + row < N) rb[p] = *(const float4*)(Bm + (size_t)(n0 + row) * K + k0 + lk);
            }
        }
#pragma unroll
        for (int kk = 0; kk < BKK; kk++) {
            float af[TM], bf[TN];
#pragma unroll
            for (int i = 0; i < TM; i++) af[i] = As[cur][kk][ty * TM + i];
#pragma unroll
            for (int j = 0; j < TN; j++) bf[j] = Bs[cur][kk][tx * TN + j];
#pragma unroll
            for (int i = 0; i < TM; i++)
#pragma unroll
                for (int j = 0; j < TN; j++) acc[i][j] += af[i] * bf[j];
        }
        if (haveNext) {
            int nxt = cur ^ 1;
#pragma unroll
            for (int p = 0; p < 2; p++) {
                int row = lr + p * 64;
                As[nxt][lk + 0][row] = ra[p].x; As[nxt][lk + 1][row] = ra[p].y;
                As[nxt][lk + 2][row] = ra[p].z; As[nxt][lk + 3][row] = ra[p].w;
                Bs[nxt][lk + 0][row] = rb[p].x; Bs[nxt][lk + 1][row] = rb[p].y;
                Bs[nxt][lk + 2][row] = rb[p].z; Bs[nxt][lk + 3][row] = rb[p].w;
            }
            __syncthreads();
            cur = nxt;
        }
    }
#pragma unroll
    for (int i = 0; i < TM; i++) {
        int m = m0 + ty * TM + i;
        if (m >= M) continue;
#pragma unroll
        for (int j = 0; j < TN; j++) {
            int n = n0 + tx * TN + j;
            if (n < N) Out[(size_t)m * N + n] = acc[i][j];
        }
    }
}

// ---------------- per-pixel squared norms for q AND k in one launch ----------------
__global__ void pixnorm2(const float* __restrict__ Q, const float* __restrict__ Kt,
                         float* __restrict__ nq, float* __restrict__ nk) {
    int gr = blockIdx.x * (blockDim.x >> 5) + (threadIdx.x >> 5);
    if (gr >= 2 * B_ * L_) return;
    const float* X = (gr < B_ * L_) ? Q : Kt;
    float* n = (gr < B_ * L_) ? nq : nk;
    int row = (gr < B_ * L_) ? gr : gr - B_ * L_;
    int lane = threadIdx.x & 31;
    const float4* r = (const float4*)(X + (size_t)row * C_);
    float s = 0.f;
    for (int c4 = lane; c4 < C_ / 4; c4 += 32) {
        float4 v = r[c4];
        s += v.x * v.x + v.y * v.y + v.z * v.z + v.w * v.w;
    }
#pragma unroll
    for (int o = 16; o > 0; o >>= 1) s += __shfl_down_sync(0xffffffffu, s, o);
    if (lane == 0) n[row] = s;
}

// ---------------- 3x3 box-sum of pixel norms -> inverse patch norm (both) ----------------
__global__ void patchnorm2(const float* __restrict__ nq, const float* __restrict__ nk,
                           float* __restrict__ invq, float* __restrict__ invk) {
    int idx = blockIdx.x * blockDim.x + threadIdx.x;
    if (idx >= 2 * B_ * L_) return;
    const float* n = (idx < B_ * L_) ? nq : nk;
    float* inv = (idx < B_ * L_) ? invq : invk;
    int id = (idx < B_ * L_) ? idx : idx - B_ * L_;
    int b = id / L_, l = id % L_;
    int li = l / W_, lj = l % W_;
    float s = 0.f;
#pragma unroll
    for (int oi = -1; oi <= 1; oi++)
#pragma unroll
        for (int oj = -1; oj <= 1; oj++) {
            int a = li + oi, c = lj + oj;
            if ((unsigned)a < H_ && (unsigned)c < W_) s += n[b * L_ + a * W_ + c];
        }
    inv[id] = 1.f / fmaxf(sqrtf(s), 1e-12f);
}

// ---------------- patch-correlation stencil + argmax over l per m ----------------
__global__ void argmax_kernel(const float* __restrict__ G,
                              const float* __restrict__ ink,
                              const float* __restrict__ inq,
                              float* __restrict__ S, int* __restrict__ Arg) {
    int b = blockIdx.y, m = blockIdx.x;
    const float* Gb = G + (size_t)b * L_ * L_;
    int mi = m / W_, mj = m % W_;
    float invq = inq[b * L_ + m];
    float best = -1e30f;
    int bi = 1 << 30;
    int tid = threadIdx.x;
    for (int l = tid; l < L_; l += blockDim.x) {
        int li = l / W_, lj = l % W_;
        float P = 0.f;
#pragma unroll
        for (int oi = -1; oi <= 1; oi++)
#pragma unroll
            for (int oj = -1; oj <= 1; oj++) {
                int a = li + oi, c = lj + oj, d = mi + oi, e = mj + oj;
                if ((unsigned)a < H_ && (unsigned)c < W_ &&
                    (unsigned)d < H_ && (unsigned)e < W_)
                    P += Gb[(size_t)(a * W_ + c) * L_ + (d * W_ + e)];
            }
        float Rv = P * ink[b * L_ + l] * invq;
        if (Rv > best) { best = Rv; bi = l; }   // strict >: keeps first occurrence
    }
    __shared__ float sb[256];
    __shared__ int si[256];
    sb[tid] = best; si[tid] = bi;
    __syncthreads();
    for (int s = 128; s > 0; s >>= 1) {
        if (tid < s) {
            if (sb[tid + s] > sb[tid] ||
                (sb[tid + s] == sb[tid] && si[tid + s] < si[tid])) {
                sb[tid] = sb[tid + s]; si[tid] = si[tid + s];
            }
        }
        __syncthreads();
    }
    if (tid == 0) { S[b * L_ + m] = sb[0]; Arg[b * L_ + m] = si[0]; }
}

// ---------------- gather source indices per output pixel (fold semantics) ----------------
__global__ void srcidx_kernel(const int* __restrict__ Arg, int* __restrict__ Src) {
    int idx = blockIdx.x * blockDim.x + threadIdx.x;
    if (idx >= B_ * L_) return;
    int b = idx / L_, y = idx % L_;
    int yi = y / W_, yj = y % W_;
#pragma unroll
    for (int di = -1; di <= 1; di++)
#pragma unroll
        for (int dj = -1; dj <= 1; dj++) {
            int jj = (di + 1) * 3 + (dj + 1);
            int s = -1;
            int mi = yi + di, mj = yj + dj;
            if ((unsigned)mi < H_ && (unsigned)mj < W_) {
                int ls = Arg[b * L_ + mi * W_ + mj];
                int si = ls / W_ - di, sj = ls % W_ - dj;
                if ((unsigned)si < H_ && (unsigned)sj < W_) s = si * W_ + sj;
            }
            Src[idx * 9 + jj] = s;
        }
}

// ---------------- T_part gather: T[b][y][c] = (1/9) sum_j k[b][src_j][c] ----------------
__global__ void gather_kernel(const float* __restrict__ Kt,
                              const int* __restrict__ Src,
                              float* __restrict__ T) {
    int b = blockIdx.y, y = blockIdx.x;
    int s[9];
#pragma unroll
    for (int j = 0; j < 9; j++) s[j] = Src[((size_t)b * L_ + y) * 9 + j];
    const float* kb = Kt + (size_t)b * L_ * C_;
    float4* out = (float4*)(T + ((size_t)b * L_ + y) * C_);
    for (int c4 = threadIdx.x; c4 < C_ / 4; c4 += blockDim.x) {
        float4 acc = make_float4(0.f, 0.f, 0.f, 0.f);
#pragma unroll
        for (int j = 0; j < 9; j++) {
            if (s[j] >= 0) {
                float4 v = ((const float4*)(kb + (size_t)s[j] * C_))[c4];
                acc.x += v.x; acc.y += v.y; acc.z += v.z; acc.w += v.w;
            }
        }
        const float inv9 = 1.f / 9.f;
        acc.x *= inv9; acc.y *= inv9; acc.z *= inv9; acc.w *= inv9;
        out[c4] = acc;
    }
}

// ---------------- final fused conv: out = (wt·[q;T] + bt)*S + part_target ----------------
__global__ __launch_bounds__(256, 2)
void gemm_final(const float* __restrict__ Wt,   // [2048][4096]
                const float* __restrict__ Q,    // [b][y][c]
                const float* __restrict__ T,    // [b][y][c]
                const float* __restrict__ bt,
                const float* __restrict__ S,    // [b][y]
                const float* __restrict__ ptgt, // [b][c][y]
                float* __restrict__ Out) {      // [b][c][y]
    __shared__ float As[2][BKK][BM + 4];
    __shared__ float Bs[2][BKK][BN + 4];
    int b = blockIdx.z;
    const float* Bq = Q + (size_t)b * L_ * C_;
    const float* Bt = T + (size_t)b * L_ * C_;
    int m0 = blockIdx.y * BM, n0 = blockIdx.x * BN;
    int tid = threadIdx.x;
    int tx = tid & 15, ty = tid >> 4;
    int lr = tid >> 2;
    int lk = (tid & 3) * 4;
    float acc[TM][TN];
#pragma unroll
    for (int i = 0; i < TM; i++)
#pragma unroll
        for (int j = 0; j < TN; j++) acc[i][j] = 0.f;

    float4 ra[2], rb[2];
    // preload tile 0 (k0 = 0 -> from Q)
#pragma unroll
    for (int p = 0; p < 2; p++) {
        int row = lr + p * 64;
        ra[p] = *(const float4*)(Wt + (size_t)(m0 + row) * K2C_ + lk);
        rb[p] = make_float4(0.f, 0.f, 0.f, 0.f);
        if (n0 + row < L_) rb[p] = *(const float4*)(Bq + (size_t)(n0 + row) * C_ + lk);
    }
    int cur = 0;
#pragma unroll
    for (int p = 0; p < 2; p++) {
        int row = lr + p * 64;
        As[0][lk + 0][row] = ra[p].x; As[0][lk + 1][row] = ra[p].y;
        As[0][lk + 2][row] = ra[p].z; As[0][lk + 3][row] = ra[p].w;
        Bs[0][lk + 0][row] = rb[p].x; Bs[0][lk + 1][row] = rb[p].y;
        Bs[0][lk + 2][row] = rb[p].z; Bs[0][lk + 3][row] = rb[p].w;
    }
    __syncthreads();

    for (int k0 = BKK; k0 <= K2C_; k0 += BKK) {
        bool haveNext = (k0 < K2C_);
        if (haveNext) {
            const float* Bp; int kb;
            if (k0 < C_) { Bp = Bq; kb = k0; } else { Bp = Bt; kb = k0 - C_; }
#pragma unroll
            for (int p = 0; p < 2; p++) {
                int row = lr + p * 64;
                ra[p] = *(const float4*)(Wt + (size_t)(m0 + row) * K2C_ + k0 + lk);
                rb[p] = make_float4(0.f, 0.f, 0.f, 0.f);
                if (n0 + row < L_) rb[p] = *(const float4*)(Bp + (size_t)(n0 + row) * C_ + kb + lk);
            }
        }
#pragma unroll
        for (int kk = 0; kk < BKK; kk++) {
            float af[TM], bf[TN];
#pragma unroll
            for (int i = 0; i < TM; i++) af[i] = As[cur][kk][ty * TM + i];
#pragma unroll
            for (int j = 0; j < TN; j++) bf[j] = Bs[cur][kk][tx * TN + j];
#pragma unroll
            for (int i = 0; i < TM; i++)
#pragma unroll
                for (int j = 0; j < TN; j++) acc[i][j] += af[i] * bf[j];
        }
        if (haveNext) {
            int nxt = cur ^ 1;
#pragma unroll
            for (int p = 0; p < 2; p++) {
                int row = lr + p * 64;
                As[nxt][lk + 0][row] = ra[p].x; As[nxt][lk + 1][row] = ra[p].y;
                As[nxt][lk + 2][row] = ra[p].z; As[nxt][lk + 3][row] = ra[p].w;
                Bs[nxt][lk + 0][row] = rb[p].x; Bs[nxt][lk + 1][row] = rb[p].y;
                Bs[nxt][lk + 2][row] = rb[p].z; Bs[nxt][lk + 3][row] = rb[p].w;
            }
            __syncthreads();
            cur = nxt;
        }
    }
#pragma unroll
    for (int i = 0; i < TM; i++) {
        int m = m0 + ty * TM + i;    // channel
        float bias = bt[m];
#pragma unroll
        for (int j = 0; j < TN; j++) {
            int n = n0 + tx * TN + j;  // pixel
            if (n < L_) {
                size_t o = ((size_t)b * C_ + m) * L_ + n;
                Out[o] = (acc[i][j] + bias) * S[b * L_ + n] + ptgt[o];
            }
        }
    }
}

// ---------------- launch ----------------
extern "C" void kernel_launch(void* const* d_in, const int* in_sizes, int n_in,
                              void* d_out, int out_size) {
    const float* part_ref = (const float*)d_in[0];
    const float* part_tgt = (const float*)d_in[1];
    const float* wq = (const float*)d_in[2];
    const float* bq = (const float*)d_in[3];
    const float* wk = (const float*)d_in[4];
    const float* bk = (const float*)d_in[5];
    const float* wt = (const float*)d_in[6];
    const float* bt = (const float*)d_in[7];
    float* out = (float*)d_out;

    float *xt_ref, *xt_tgt, *q, *k, *G, *nq, *nk, *inq, *ink, *S, *T;
    int *arg, *src;
    cudaGetSymbolAddress((void**)&xt_ref, g_xt_ref);
    cudaGetSymbolAddress((void**)&xt_tgt, g_xt_tgt);
    cudaGetSymbolAddress((void**)&q, g_q);
    cudaGetSymbolAddress((void**)&k, g_k);
    cudaGetSymbolAddress((void**)&G, g_G);
    cudaGetSymbolAddress((void**)&nq, g_nq);
    cudaGetSymbolAddress((void**)&nk, g_nk);
    cudaGetSymbolAddress((void**)&inq, g_inq);
    cudaGetSymbolAddress((void**)&ink, g_ink);
    cudaGetSymbolAddress((void**)&S, g_S);
    cudaGetSymbolAddress((void**)&T, g_T);
    cudaGetSymbolAddress((void**)&arg, g_arg);
    cudaGetSymbolAddress((void**)&src, g_src);

    dim3 tb(32, 8);
    dim3 tg(L_ / 32, C_ / 32, B_);
    transpose_cl_lc<<<tg, tb>>>(part_ref, xt_ref);
    transpose_cl_lc<<<tg, tb>>>(part_tgt, xt_tgt);

    // fused q & k projections: grid.z in [0, 2B)
    dim3 gqk((C_ + BN - 1) / BN, (L_ + BM - 1) / BM, 2 * B_);
    gemm_qk<<<gqk, 256>>>(xt_tgt, xt_ref, wq, bq, wk, bk, q, k);

    // per-pixel squared norms (q and k fused)
    pixnorm2<<<(2 * B_ * L_ + 7) / 8, 256>>>(q, k, nq, nk);
    patchnorm2<<<(2 * B_ * L_ + 255) / 256, 256>>>(nq, nk, inq, ink);

    // pixel Gram G[b][l][m] = k[l]·q[m]
    dim3 gg((L_ + BN - 1) / BN, (L_ + BM - 1) / BM, B_);
    gemm_gram<<<gg, 256>>>(k, q, G);

    // patch correlation stencil + argmax
    dim3 ga(L_, B_);
    argmax_kernel<<<ga, 256>>>(G, ink, inq, S, arg);

    srcidx_kernel<<<(B_ * L_ + 255) / 256, 256>>>(arg, src);
    gather_kernel<<<dim3(L_, B_), 256>>>(k, src, T);

    // final fused conv + scale + residual
    dim3 gf((L_ + BN - 1) / BN, (C_ + BM - 1) / BM, B_);
    gemm_final<<<gf, 256>>>(wt, q, T, bt, S, part_tgt, out);
}

// round 3
// speedup vs baseline: 1.0035x; 1.0035x over previous
#include <cuda_runtime.h>
#include <math.h>

// Problem constants
#define B_ 4
#define C_ 2048
#define H_ 24
#define W_ 24
#define L_ 576            // H_*W_
#define K2C_ 4096         // 2*C_

// ---------------- scratch (device globals; no allocation allowed) ----------------
__device__ float g_xt_ref[B_ * L_ * C_];   // part_ref transposed   [b][l][c]
__device__ float g_xt_tgt[B_ * L_ * C_];   // part_target transposed [b][l][c]
__device__ float g_q[B_ * L_ * C_];        // q = Wq x_tgt + bq     [b][l][c]
__device__ float g_k[B_ * L_ * C_];        // k = Wk x_ref + bk     [b][l][c]
__device__ float g_G[B_ * L_ * L_];        // pixel Gram k·q        [b][l][m]
__device__ float g_nq[B_ * L_];            // per-pixel sq norm of q
__device__ float g_nk[B_ * L_];            // per-pixel sq norm of k
__device__ float g_inq[B_ * L_];           // 1/max(sqrt(patch-sum nq), eps)
__device__ float g_ink[B_ * L_];
__device__ float g_S[B_ * L_];             // R_star
__device__ int   g_arg[B_ * L_];           // argmax l per m
__device__ int   g_src[B_ * L_ * 9];       // gather source rows (or -1)
__device__ float g_T[B_ * L_ * C_];        // T_part               [b][y][c]

// ---------------- transpose [b][c][l] -> [b][l][c] ----------------
__global__ void transpose_cl_lc(const float* __restrict__ in, float* __restrict__ out) {
    __shared__ float t[32][33];
    int b = blockIdx.z;
    int l0 = blockIdx.x * 32, c0 = blockIdx.y * 32;
    const float* inb = in + (size_t)b * C_ * L_;
    float* outb = out + (size_t)b * L_ * C_;
    int tx = threadIdx.x, ty = threadIdx.y;
#pragma unroll
    for (int j = 0; j < 32; j += 8)
        t[ty + j][tx] = inb[(size_t)(c0 + ty + j) * L_ + (l0 + tx)];
    __syncthreads();
#pragma unroll
    for (int j = 0; j < 32; j += 8)
        outb[(size_t)(l0 + ty + j) * C_ + (c0 + tx)] = t[tx][ty + j];
}

// ---------------- tiling params ----------------
#define BM 128
#define BN 128
#define BKK 16
#define TM 8
#define TN 8

// =====================================================================
// Double-buffered NT GEMM core (A[m][k], B[n][k] row-major K-fastest).
// Each thread loads 1 float4 of A-tile and 1 float4 of B-tile per K-step.
// One __syncthreads per mainloop iteration.
// =====================================================================

// ---- fused q/k projection: z<B -> q=Wq*xt_tgt+bq ; z>=B -> k=Wk*xt_ref+bk
__global__ __launch_bounds__(256, 2)
void gemm_qk(const float* __restrict__ XT_tgt, const float* __restrict__ XT_ref,
             const float* __restrict__ Wq, const float* __restrict__ Bq,
             const float* __restrict__ Wk, const float* __restrict__ Bk,
             float* __restrict__ Qo, float* __restrict__ Ko) {
    __shared__ float As[2][BKK][BM + 4];
    __shared__ float Bs[2][BKK][BN + 4];
    int z = blockIdx.z;
    int b = z & 3;
    bool isQ = z < B_;
    const float* A = (isQ ? XT_tgt : XT_ref) + (size_t)b * L_ * C_;  // [L][C]
    const float* Wm = isQ ? Wq : Wk;                                  // [C][C]
    const float* bias = isQ ? Bq : Bk;
    float* Out = (isQ ? Qo : Ko) + (size_t)b * L_ * C_;               // [L][C]
    const int M = L_, N = C_, K = C_;

    int m0 = blockIdx.y * BM, n0 = blockIdx.x * BN;
    int tid = threadIdx.x;
    int tx = tid & 15, ty = tid >> 4;
    int lr = tid >> 2;           // 0..63
    int lk = (tid & 3) * 4;      // 0,4,8,12
    float acc[TM][TN];
#pragma unroll
    for (int i = 0; i < TM; i++)
#pragma unroll
        for (int j = 0; j < TN; j++) acc[i][j] = 0.f;

    // preload tile 0
    float4 ra[2], rb[2];
#pragma unroll
    for (int p = 0; p < 2; p++) {
        int row = lr + p * 64;
        ra[p] = make_float4(0.f, 0.f, 0.f, 0.f);
        if (m0 + row < M) ra[p] = *(const float4*)(A + (size_t)(m0 + row) * K + lk);
        rb[p] = *(const float4*)(Wm + (size_t)(n0 + row) * K + lk);
    }
    int cur = 0;
#pragma unroll
    for (int p = 0; p < 2; p++) {
        int row = lr + p * 64;
        As[0][lk + 0][row] = ra[p].x; As[0][lk + 1][row] = ra[p].y;
        As[0][lk + 2][row] = ra[p].z; As[0][lk + 3][row] = ra[p].w;
        Bs[0][lk + 0][row] = rb[p].x; Bs[0][lk + 1][row] = rb[p].y;
        Bs[0][lk + 2][row] = rb[p].z; Bs[0][lk + 3][row] = rb[p].w;
    }
    __syncthreads();

    for (int k0 = BKK; k0 <= K; k0 += BKK) {
        bool haveNext = (k0 < K);
        if (haveNext) {
#pragma unroll
            for (int p = 0; p < 2; p++) {
                int row = lr + p * 64;
                ra[p] = make_float4(0.f, 0.f, 0.f, 0.f);
                if (m0 + row < M) ra[p] = *(const float4*)(A + (size_t)(m0 + row) * K + k0 + lk);
                rb[p] = *(const float4*)(Wm + (size_t)(n0 + row) * K + k0 + lk);
            }
        }
#pragma unroll
        for (int kk = 0; kk < BKK; kk++) {
            float af[TM], bf[TN];
#pragma unroll
            for (int i = 0; i < TM; i++) af[i] = As[cur][kk][ty * TM + i];
#pragma unroll
            for (int j = 0; j < TN; j++) bf[j] = Bs[cur][kk][tx * TN + j];
#pragma unroll
            for (int i = 0; i < TM; i++)
#pragma unroll
                for (int j = 0; j < TN; j++) acc[i][j] += af[i] * bf[j];
        }
        if (haveNext) {
            int nxt = cur ^ 1;
#pragma unroll
            for (int p = 0; p < 2; p++) {
                int row = lr + p * 64;
                As[nxt][lk + 0][row] = ra[p].x; As[nxt][lk + 1][row] = ra[p].y;
                As[nxt][lk + 2][row] = ra[p].z; As[nxt][lk + 3][row] = ra[p].w;
                Bs[nxt][lk + 0][row] = rb[p].x; Bs[nxt][lk + 1][row] = rb[p].y;
                Bs[nxt][lk + 2][row] = rb[p].z; Bs[nxt][lk + 3][row] = rb[p].w;
            }
            __syncthreads();
            cur = nxt;
        }
    }
#pragma unroll
    for (int i = 0; i < TM; i++) {
        int m = m0 + ty * TM + i;
        if (m >= M) continue;
#pragma unroll
        for (int j = 0; j < TN; j++) {
            int n = n0 + tx * TN + j;
            Out[(size_t)m * N + n] = acc[i][j] + bias[n];
        }
    }
}

// ---- Gram GEMM: G[b][l][m] = sum_c k[b][l][c] * q[b][m][c]   (M=N=L, K=C)
__global__ __launch_bounds__(256, 2)
void gemm_gram(const float* __restrict__ Kt, const float* __restrict__ Qt,
               float* __restrict__ G) {
    __shared__ float As[2][BKK][BM + 4];
    __shared__ float Bs[2][BKK][BN + 4];
    int b = blockIdx.z;
    const float* A = Kt + (size_t)b * L_ * C_;
    const float* Bm = Qt + (size_t)b * L_ * C_;
    float* Out = G + (size_t)b * L_ * L_;
    const int M = L_, N = L_, K = C_;

    int m0 = blockIdx.y * BM, n0 = blockIdx.x * BN;
    int tid = threadIdx.x;
    int tx = tid & 15, ty = tid >> 4;
    int lr = tid >> 2;
    int lk = (tid & 3) * 4;
    float acc[TM][TN];
#pragma unroll
    for (int i = 0; i < TM; i++)
#pragma unroll
        for (int j = 0; j < TN; j++) acc[i][j] = 0.f;

    float4 ra[2], rb[2];
#pragma unroll
    for (int p = 0; p < 2; p++) {
        int row = lr + p * 64;
        ra[p] = make_float4(0.f, 0.f, 0.f, 0.f);
        rb[p] = ra[p];
        if (m0 + row < M) ra[p] = *(const float4*)(A + (size_t)(m0 + row) * K + lk);
        if (n0 + row < N) rb[p] = *(const float4*)(Bm + (size_t)(n0 + row) * K + lk);
    }
    int cur = 0;
#pragma unroll
    for (int p = 0; p < 2; p++) {
        int row = lr + p * 64;
        As[0][lk + 0][row] = ra[p].x; As[0][lk + 1][row] = ra[p].y;
        As[0][lk + 2][row] = ra[p].z; As[0][lk + 3][row] = ra[p].w;
        Bs[0][lk + 0][row] = rb[p].x; Bs[0][lk + 1][row] = rb[p].y;
        Bs[0][lk + 2][row] = rb[p].z; Bs[0][lk + 3][row] = rb[p].w;
    }
    __syncthreads();

    for (int k0 = BKK; k0 <= K; k0 += BKK) {
        bool haveNext = (k0 < K);
        if (haveNext) {
#pragma unroll
            for (int p = 0; p < 2; p++) {
                int row = lr + p * 64;
                ra[p] = make_float4(0.f, 0.f, 0.f, 0.f);
                rb[p] = ra[p];
                if (m0 + row < M) ra[p] = *(const float4*)(A + (size_t)(m0 + row) * K + k0 + lk);
                if (n0 + row < N) rb[p] = *(const float4*)(Bm + (size_t)(n0 + row) * K + k0 + lk);
            }
        }
#pragma unroll
        for (int kk = 0; kk < BKK; kk++) {
            float af[TM], bf[TN];
#pragma unroll
            for (int i = 0; i < TM; i++) af[i] = As[cur][kk][ty * TM + i];
#pragma unroll
            for (int j = 0; j < TN; j++) bf[j] = Bs[cur][kk][tx * TN + j];
#pragma unroll
            for (int i = 0; i < TM; i++)
#pragma unroll
                for (int j = 0; j < TN; j++) acc[i][j] += af[i] * bf[j];
        }
        if (haveNext) {
            int nxt = cur ^ 1;
#pragma unroll
            for (int p = 0; p < 2; p++) {
                int row = lr + p * 64;
                As[nxt][lk + 0][row] = ra[p].x; As[nxt][lk + 1][row] = ra[p].y;
                As[nxt][lk + 2][row] = ra[p].z; As[nxt][lk + 3][row] = ra[p].w;
                Bs[nxt][lk + 0][row] = rb[p].x; Bs[nxt][lk + 1][row] = rb[p].y;
                Bs[nxt][lk + 2][row] = rb[p].z; Bs[nxt][lk + 3][row] = rb[p].w;
            }
            __syncthreads();
            cur = nxt;
        }
    }
#pragma unroll
    for (int i = 0; i < TM; i++) {
        int m = m0 + ty * TM + i;
        if (m >= M) continue;
#pragma unroll
        for (int j = 0; j < TN; j++) {
            int n = n0 + tx * TN + j;
            if (n < N) Out[(size_t)m * N + n] = acc[i][j];
        }
    }
}

// ---------------- per-pixel squared norms for q AND k in one launch ----------------
__global__ void pixnorm2(const float* __restrict__ Q, const float* __restrict__ Kt,
                         float* __restrict__ nq, float* __restrict__ nk) {
    int gr = blockIdx.x * (blockDim.x >> 5) + (threadIdx.x >> 5);
    if (gr >= 2 * B_ * L_) return;
    const float* X = (gr < B_ * L_) ? Q : Kt;
    float* n = (gr < B_ * L_) ? nq : nk;
    int row = (gr < B_ * L_) ? gr : gr - B_ * L_;
    int lane = threadIdx.x & 31;
    const float4* r = (const float4*)(X + (size_t)row * C_);
    float s = 0.f;
    for (int c4 = lane; c4 < C_ / 4; c4 += 32) {
        float4 v = r[c4];
        s += v.x * v.x + v.y * v.y + v.z * v.z + v.w * v.w;
    }
#pragma unroll
    for (int o = 16; o > 0; o >>= 1) s += __shfl_down_sync(0xffffffffu, s, o);
    if (lane == 0) n[row] = s;
}

// ---------------- 3x3 box-sum of pixel norms -> inverse patch norm (both) ----------------
__global__ void patchnorm2(const float* __restrict__ nq, const float* __restrict__ nk,
                           float* __restrict__ invq, float* __restrict__ invk) {
    int idx = blockIdx.x * blockDim.x + threadIdx.x;
    if (idx >= 2 * B_ * L_) return;
    const float* n = (idx < B_ * L_) ? nq : nk;
    float* inv = (idx < B_ * L_) ? invq : invk;
    int id = (idx < B_ * L_) ? idx : idx - B_ * L_;
    int b = id / L_, l = id % L_;
    int li = l / W_, lj = l % W_;
    float s = 0.f;
#pragma unroll
    for (int oi = -1; oi <= 1; oi++)
#pragma unroll
        for (int oj = -1; oj <= 1; oj++) {
            int a = li + oi, c = lj + oj;
            if ((unsigned)a < H_ && (unsigned)c < W_) s += n[b * L_ + a * W_ + c];
        }
    inv[id] = 1.f / fmaxf(sqrtf(s), 1e-12f);
}

// ---------------- patch-correlation stencil + argmax over l per m ----------------
__global__ void argmax_kernel(const float* __restrict__ G,
                              const float* __restrict__ ink,
                              const float* __restrict__ inq,
                              float* __restrict__ S, int* __restrict__ Arg) {
    int b = blockIdx.y, m = blockIdx.x;
    const float* Gb = G + (size_t)b * L_ * L_;
    int mi = m / W_, mj = m % W_;
    float invq = inq[b * L_ + m];
    float best = -1e30f;
    int bi = 1 << 30;
    int tid = threadIdx.x;
    for (int l = tid; l < L_; l += blockDim.x) {
        int li = l / W_, lj = l % W_;
        float P = 0.f;
#pragma unroll
        for (int oi = -1; oi <= 1; oi++)
#pragma unroll
            for (int oj = -1; oj <= 1; oj++) {
                int a = li + oi, c = lj + oj, d = mi + oi, e = mj + oj;
                if ((unsigned)a < H_ && (unsigned)c < W_ &&
                    (unsigned)d < H_ && (unsigned)e < W_)
                    P += Gb[(size_t)(a * W_ + c) * L_ + (d * W_ + e)];
            }
        float Rv = P * ink[b * L_ + l] * invq;
        if (Rv > best) { best = Rv; bi = l; }   // strict >: keeps first occurrence
    }
    __shared__ float sb[256];
    __shared__ int si[256];
    sb[tid] = best; si[tid] = bi;
    __syncthreads();
    for (int s = 128; s > 0; s >>= 1) {
        if (tid < s) {
            if (sb[tid + s] > sb[tid] ||
                (sb[tid + s] == sb[tid] && si[tid + s] < si[tid])) {
                sb[tid] = sb[tid + s]; si[tid] = si[tid + s];
            }
        }
        __syncthreads();
    }
    if (tid == 0) { S[b * L_ + m] = sb[0]; Arg[b * L_ + m] = si[0]; }
}

// ---------------- gather source indices per output pixel (fold semantics) ----------------
__global__ void srcidx_kernel(const int* __restrict__ Arg, int* __restrict__ Src) {
    int idx = blockIdx.x * blockDim.x + threadIdx.x;
    if (idx >= B_ * L_) return;
    int b = idx / L_, y = idx % L_;
    int yi = y / W_, yj = y % W_;
#pragma unroll
    for (int di = -1; di <= 1; di++)
#pragma unroll
        for (int dj = -1; dj <= 1; dj++) {
            int jj = (di + 1) * 3 + (dj + 1);
            int s = -1;
            int mi = yi + di, mj = yj + dj;
            if ((unsigned)mi < H_ && (unsigned)mj < W_) {
                int ls = Arg[b * L_ + mi * W_ + mj];
                int si = ls / W_ - di, sj = ls % W_ - dj;
                if ((unsigned)si < H_ && (unsigned)sj < W_) s = si * W_ + sj;
            }
            Src[idx * 9 + jj] = s;
        }
}

// ---------------- T_part gather: T[b][y][c] = (1/9) sum_j k[b][src_j][c] ----------------
__global__ void gather_kernel(const float* __restrict__ Kt,
                              const int* __restrict__ Src,
                              float* __restrict__ T) {
    int b = blockIdx.y, y = blockIdx.x;
    int s[9];
#pragma unroll
    for (int j = 0; j < 9; j++) s[j] = Src[((size_t)b * L_ + y) * 9 + j];
    const float* kb = Kt + (size_t)b * L_ * C_;
    float4* out = (float4*)(T + ((size_t)b * L_ + y) * C_);
    for (int c4 = threadIdx.x; c4 < C_ / 4; c4 += blockDim.x) {
        float4 acc = make_float4(0.f, 0.f, 0.f, 0.f);
#pragma unroll
        for (int j = 0; j < 9; j++) {
            if (s[j] >= 0) {
                float4 v = ((const float4*)(kb + (size_t)s[j] * C_))[c4];
                acc.x += v.x; acc.y += v.y; acc.z += v.z; acc.w += v.w;
            }
        }
        const float inv9 = 1.f / 9.f;
        acc.x *= inv9; acc.y *= inv9; acc.z *= inv9; acc.w *= inv9;
        out[c4] = acc;
    }
}

// ---------------- final fused conv: out = (wt·[q;T] + bt)*S + part_target ----------------
__global__ __launch_bounds__(256, 2)
void gemm_final(const float* __restrict__ Wt,   // [2048][4096]
                const float* __restrict__ Q,    // [b][y][c]
                const float* __restrict__ T,    // [b][y][c]
                const float* __restrict__ bt,
                const float* __restrict__ S,    // [b][y]
                const float* __restrict__ ptgt, // [b][c][y]
                float* __restrict__ Out) {      // [b][c][y]
    __shared__ float As[2][BKK][BM + 4];
    __shared__ float Bs[2][BKK][BN + 4];
    int b = blockIdx.z;
    const float* Bq = Q + (size_t)b * L_ * C_;
    const float* Bt = T + (size_t)b * L_ * C_;
    int m0 = blockIdx.y * BM, n0 = blockIdx.x * BN;
    int tid = threadIdx.x;
    int tx = tid & 15, ty = tid >> 4;
    int lr = tid >> 2;
    int lk = (tid & 3) * 4;
    float acc[TM][TN];
#pragma unroll
    for (int i = 0; i < TM; i++)
#pragma unroll
        for (int j = 0; j < TN; j++) acc[i][j] = 0.f;

    float4 ra[2], rb[2];
    // preload tile 0 (k0 = 0 -> from Q)
#pragma unroll
    for (int p = 0; p < 2; p++) {
        int row = lr + p * 64;
        ra[p] = *(const float4*)(Wt + (size_t)(m0 + row) * K2C_ + lk);
        rb[p] = make_float4(0.f, 0.f, 0.f, 0.f);
        if (n0 + row < L_) rb[p] = *(const float4*)(Bq + (size_t)(n0 + row) * C_ + lk);
    }
    int cur = 0;
#pragma unroll
    for (int p = 0; p < 2; p++) {
        int row = lr + p * 64;
        As[0][lk + 0][row] = ra[p].x; As[0][lk + 1][row] = ra[p].y;
        As[0][lk + 2][row] = ra[p].z; As[0][lk + 3][row] = ra[p].w;
        Bs[0][lk + 0][row] = rb[p].x; Bs[0][lk + 1][row] = rb[p].y;
        Bs[0][lk + 2][row] = rb[p].z; Bs[0][lk + 3][row] = rb[p].w;
    }
    __syncthreads();

    for (int k0 = BKK; k0 <= K2C_; k0 += BKK) {
        bool haveNext = (k0 < K2C_);
        if (haveNext) {
            const float* Bp; int kb;
            if (k0 < C_) { Bp = Bq; kb = k0; } else { Bp = Bt; kb = k0 - C_; }
#pragma unroll
            for (int p = 0; p < 2; p++) {
                int row = lr + p * 64;
                ra[p] = *(const float4*)(Wt + (size_t)(m0 + row) * K2C_ + k0 + lk);
                rb[p] = make_float4(0.f, 0.f, 0.f, 0.f);
                if (n0 + row < L_) rb[p] = *(const float4*)(Bp + (size_t)(n0 + row) * C_ + kb + lk);
            }
        }
#pragma unroll
        for (int kk = 0; kk < BKK; kk++) {
            float af[TM], bf[TN];
#pragma unroll
            for (int i = 0; i < TM; i++) af[i] = As[cur][kk][ty * TM + i];
#pragma unroll
            for (int j = 0; j < TN; j++) bf[j] = Bs[cur][kk][tx * TN + j];
#pragma unroll
            for (int i = 0; i < TM; i++)
#pragma unroll
                for (int j = 0; j < TN; j++) acc[i][j] += af[i] * bf[j];
        }
        if (haveNext) {
            int nxt = cur ^ 1;
#pragma unroll
            for (int p = 0; p < 2; p++) {
                int row = lr + p * 64;
                As[nxt][lk + 0][row] = ra[p].x; As[nxt][lk + 1][row] = ra[p].y;
                As[nxt][lk + 2][row] = ra[p].z; As[nxt][lk + 3][row] = ra[p].w;
                Bs[nxt][lk + 0][row] = rb[p].x; Bs[nxt][lk + 1][row] = rb[p].y;
                Bs[nxt][lk + 2][row] = rb[p].z; Bs[nxt][lk + 3][row] = rb[p].w;
            }
            __syncthreads();
            cur = nxt;
        }
    }
#pragma unroll
    for (int i = 0; i < TM; i++) {
        int m = m0 + ty * TM + i;    // channel
        float bias = bt[m];
#pragma unroll
        for (int j = 0; j < TN; j++) {
            int n = n0 + tx * TN + j;  // pixel
            if (n < L_) {
                size_t o = ((size_t)b * C_ + m) * L_ + n;
                Out[o] = (acc[i][j] + bias) * S[b * L_ + n] + ptgt[o];
            }
        }
    }
}

// ---------------- launch ----------------
extern "C" void kernel_launch(void* const* d_in, const int* in_sizes, int n_in,
                              void* d_out, int out_size) {
    const float* part_ref = (const float*)d_in[0];
    const float* part_tgt = (const float*)d_in[1];
    const float* wq = (const float*)d_in[2];
    const float* bq = (const float*)d_in[3];
    const float* wk = (const float*)d_in[4];
    const float* bk = (const float*)d_in[5];
    const float* wt = (const float*)d_in[6];
    const float* bt = (const float*)d_in[7];
    float* out = (float*)d_out;

    float *xt_ref, *xt_tgt, *q, *k, *G, *nq, *nk, *inq, *ink, *S, *T;
    int *arg, *src;
    cudaGetSymbolAddress((void**)&xt_ref, g_xt_ref);
    cudaGetSymbolAddress((void**)&xt_tgt, g_xt_tgt);
    cudaGetSymbolAddress((void**)&q, g_q);
    cudaGetSymbolAddress((void**)&k, g_k);
    cudaGetSymbolAddress((void**)&G, g_G);
    cudaGetSymbolAddress((void**)&nq, g_nq);
    cudaGetSymbolAddress((void**)&nk, g_nk);
    cudaGetSymbolAddress((void**)&inq, g_inq);
    cudaGetSymbolAddress((void**)&ink, g_ink);
    cudaGetSymbolAddress((void**)&S, g_S);
    cudaGetSymbolAddress((void**)&T, g_T);
    cudaGetSymbolAddress((void**)&arg, g_arg);
    cudaGetSymbolAddress((void**)&src, g_src);

    dim3 tb(32, 8);
    dim3 tg(L_ / 32, C_ / 32, B_);
    transpose_cl_lc<<<tg, tb>>>(part_ref, xt_ref);
    transpose_cl_lc<<<tg, tb>>>(part_tgt, xt_tgt);

    // fused q & k projections: grid.z in [0, 2B)
    dim3 gqk((C_ + BN - 1) / BN, (L_ + BM - 1) / BM, 2 * B_);
    gemm_qk<<<gqk, 256>>>(xt_tgt, xt_ref, wq, bq, wk, bk, q, k);

    // per-pixel squared norms (q and k fused)
    pixnorm2<<<(2 * B_ * L_ + 7) / 8, 256>>>(q, k, nq, nk);
    patchnorm2<<<(2 * B_ * L_ + 255) / 256, 256>>>(nq, nk, inq, ink);

    // pixel Gram G[b][l][m] = k[l]·q[m]
    dim3 gg((L_ + BN - 1) / BN, (L_ + BM - 1) / BM, B_);
    gemm_gram<<<gg, 256>>>(k, q, G);

    // patch correlation stencil + argmax
    dim3 ga(L_, B_);
    argmax_kernel<<<ga, 256>>>(G, ink, inq, S, arg);

    srcidx_kernel<<<(B_ * L_ + 255) / 256, 256>>>(arg, src);
    gather_kernel<<<dim3(L_, B_), 256>>>(k, src, T);

    // final fused conv + scale + residual
    dim3 gf((L_ + BN - 1) / BN, (C_ + BM - 1) / BM, B_);
    gemm_final<<<gf, 256>>>(wt, q, T, bt, S, part_tgt, out);
}

// round 8
// speedup vs baseline: 2.2521x; 2.2443x over previous
#include <cuda_runtime.h>
#include <cuda_bf16.h>
#include <math.h>
#include <stdint.h>

#define B_ 4
#define C_ 2048
#define H_ 24
#define W_ 24
#define L_ 576
#define LP_ 640
#define K2C_ 4096

// ---------------- scratch device globals ----------------
__device__ __nv_bfloat16 g_xh_t[B_*LP_*C_], g_xl_t[B_*LP_*C_];
__device__ __nv_bfloat16 g_xh_r[B_*LP_*C_], g_xl_r[B_*LP_*C_];
__device__ __nv_bfloat16 g_wqh[C_*C_], g_wql[C_*C_], g_wkh[C_*C_], g_wkl[C_*C_];
__device__ __nv_bfloat16 g_wth[C_*K2C_], g_wtl[C_*K2C_];
__device__ float g_qf[B_*L_*C_], g_kf[B_*L_*C_];
__device__ __nv_bfloat16 g_qh[B_*LP_*C_], g_ql[B_*LP_*C_];
__device__ __nv_bfloat16 g_kh[B_*LP_*C_], g_kl[B_*LP_*C_];
__device__ __nv_bfloat16 g_Th[B_*LP_*C_], g_Tl[B_*LP_*C_];
__device__ float g_G[B_*L_*L_];
__device__ float g_nq[B_*L_], g_nk[B_*L_], g_inq[B_*L_], g_ink[B_*L_], g_S[B_*L_];
__device__ int g_arg[B_*L_], g_src[B_*L_*9];

// ---------------- PTX helpers ----------------
__device__ __forceinline__ uint32_t smem_u32(const void* p) {
    uint32_t a;
    asm("{ .reg .u64 t; cvta.to.shared.u64 t, %1; cvt.u32.u64 %0, t; }" : "=r"(a) : "l"(p));
    return a;
}
#define CP16(d, s) asm volatile("cp.async.cg.shared.global [%0], [%1], 16;" :: "r"(d), "l"(s))
#define CPCOMMIT() asm volatile("cp.async.commit_group;" ::: "memory")
#define CPWAIT1()  asm volatile("cp.async.wait_group 1;" ::: "memory")
#define CPWAIT0()  asm volatile("cp.async.wait_group 0;" ::: "memory")
__device__ __forceinline__ void ldsm4(uint32_t* r, uint32_t a) {
    asm volatile("ldmatrix.sync.aligned.m8n8.x4.shared.b16 {%0,%1,%2,%3}, [%4];"
                 : "=r"(r[0]), "=r"(r[1]), "=r"(r[2]), "=r"(r[3]) : "r"(a));
}
__device__ __forceinline__ void mma16816(float* d, const uint32_t* a, const uint32_t* b) {
    asm volatile("mma.sync.aligned.m16n8k16.row.col.f32.bf16.bf16.f32 "
                 "{%0,%1,%2,%3},{%4,%5,%6,%7},{%8,%9},{%0,%1,%2,%3};"
                 : "+f"(d[0]), "+f"(d[1]), "+f"(d[2]), "+f"(d[3])
                 : "r"(a[0]), "r"(a[1]), "r"(a[2]), "r"(a[3]), "r"(b[0]), "r"(b[1]));
}

// ---------------- GEMM core: BM=BN=128, BK=32, 8 warps (2x4), warp tile 64x32 ----
// smem tile: [128 rows][32 bf16], pitch 80 bytes -> conflict-free ldmatrix.
#define TSZ 10240
#define STG (4*TSZ)

__device__ __forceinline__ void cpa_tile(uint32_t sb, const __nv_bfloat16* g, int ld, int tid) {
#pragma unroll
    for (int i = 0; i < 2; i++) {
        int idx = tid + i * 256;
        int r = idx >> 2, c = idx & 3;
        CP16(sb + r * 80 + c * 16, g + (size_t)r * ld + c * 8);
    }
}

// 3-pass split mainloop: acc += Ah*Bh + Ah*Bl + Al*Bh.
// B source switches from (Bh,Bl) to (Bh2,Bl2) at k-tile ksw (for the final conv).
__device__ void gemm_main(const __nv_bfloat16* Ah, const __nv_bfloat16* Al,
                          const __nv_bfloat16* Bh, const __nv_bfloat16* Bl,
                          const __nv_bfloat16* Bh2, const __nv_bfloat16* Bl2,
                          int lda, int ldb, int KT, int ksw, float acc[4][4][4]) {
    extern __shared__ char smem_[];
    uint32_t sb = smem_u32(smem_);
    int tid = threadIdx.x, lane = tid & 31, warp = tid >> 5;
    int wm = (warp >> 2) * 64, wn = (warp & 3) * 32;
#pragma unroll
    for (int i = 0; i < 4; i++)
#pragma unroll
        for (int j = 0; j < 4; j++)
#pragma unroll
            for (int r = 0; r < 4; r++) acc[i][j][r] = 0.f;

    int rsel = lane & 7, msel = (lane >> 3) & 1, ksel = lane >> 4;

    {
        uint32_t b0 = sb;
        cpa_tile(b0,           Ah, lda, tid);
        cpa_tile(b0 + TSZ,     Bh, ldb, tid);
        cpa_tile(b0 + 2 * TSZ, Al, lda, tid);
        cpa_tile(b0 + 3 * TSZ, Bl, ldb, tid);
        CPCOMMIT();
    }
    for (int kt = 0; kt < KT; kt++) {
        int cur = kt & 1;
        if (kt + 1 < KT) {
            int k2 = kt + 1;
            uint32_t b0 = sb + (cur ^ 1) * STG;
            const __nv_bfloat16* bh = (k2 < ksw) ? Bh + (size_t)k2 * 32 : Bh2 + (size_t)(k2 - ksw) * 32;
            const __nv_bfloat16* bl = (k2 < ksw) ? Bl + (size_t)k2 * 32 : Bl2 + (size_t)(k2 - ksw) * 32;
            cpa_tile(b0,           Ah + (size_t)k2 * 32, lda, tid);
            cpa_tile(b0 + TSZ,     bh,                   ldb, tid);
            cpa_tile(b0 + 2 * TSZ, Al + (size_t)k2 * 32, lda, tid);
            cpa_tile(b0 + 3 * TSZ, bl,                   ldb, tid);
            CPCOMMIT();
            CPWAIT1();
        } else {
            CPWAIT0();
        }
        __syncthreads();
        uint32_t b0 = sb + cur * STG;
#pragma unroll
        for (int ki = 0; ki < 2; ki++) {
            uint32_t a[4][4], al[4][4], bb[2][4], bl[2][4];
#pragma unroll
            for (int mi = 0; mi < 4; mi++) {
                uint32_t ad = (uint32_t)(wm + mi * 16 + rsel + msel * 8) * 80 + ki * 32 + ksel * 16;
                ldsm4(a[mi],  b0 + ad);
                ldsm4(al[mi], b0 + 2 * TSZ + ad);
            }
#pragma unroll
            for (int n2 = 0; n2 < 2; n2++) {
                uint32_t bd = (uint32_t)(wn + n2 * 16 + rsel + msel * 8) * 80 + ki * 32 + ksel * 16;
                ldsm4(bb[n2], b0 + TSZ + bd);
                ldsm4(bl[n2], b0 + 3 * TSZ + bd);
            }
#pragma unroll
            for (int mi = 0; mi < 4; mi++)
#pragma unroll
                for (int nj = 0; nj < 4; nj++) {
                    uint32_t bf[2]  = { bb[nj >> 1][nj & 1], bb[nj >> 1][(nj & 1) + 2] };
                    uint32_t bfl[2] = { bl[nj >> 1][nj & 1], bl[nj >> 1][(nj & 1) + 2] };
                    mma16816(acc[mi][nj], a[mi], bf);
                    mma16816(acc[mi][nj], a[mi], bfl);
                    mma16816(acc[mi][nj], al[mi], bf);
                }
        }
        __syncthreads();
    }
}

// ---------------- prep: transpose [b][c][l] -> [b][l pad 640][c], bf16 split ------
__global__ void prep_split(const float* __restrict__ in,
                           __nv_bfloat16* __restrict__ oh, __nv_bfloat16* __restrict__ ol) {
    __shared__ float t[32][33];
    int b = blockIdx.z;
    int l0 = blockIdx.x * 32, c0 = blockIdx.y * 32;
    int tx = threadIdx.x, ty = threadIdx.y;
#pragma unroll
    for (int j = 0; j < 32; j += 8) {
        int l = l0 + tx;
        t[ty + j][tx] = (l < L_) ? in[((size_t)b * C_ + c0 + ty + j) * L_ + l] : 0.f;
    }
    __syncthreads();
#pragma unroll
    for (int j = 0; j < 32; j += 8) {
        int l = l0 + ty + j, c = c0 + tx;
        float v = t[tx][ty + j];
        __nv_bfloat16 h = __float2bfloat16(v);
        size_t o = ((size_t)b * LP_ + l) * C_ + c;
        oh[o] = h;
        ol[o] = __float2bfloat16(v - __bfloat162float(h));
    }
}

// ---------------- weight splits ----------------
__global__ void split_w(const float* __restrict__ wq, const float* __restrict__ wk,
                        const float* __restrict__ wt) {
    size_t i = (size_t)blockIdx.x * 256 + threadIdx.x;
    const size_t CC = (size_t)C_ * C_;
    float v; __nv_bfloat16 h;
    if (i < CC) {
        v = wq[i]; h = __float2bfloat16(v);
        g_wqh[i] = h; g_wql[i] = __float2bfloat16(v - __bfloat162float(h));
    } else if (i < 2 * CC) {
        size_t j = i - CC;
        v = wk[j]; h = __float2bfloat16(v);
        g_wkh[j] = h; g_wkl[j] = __float2bfloat16(v - __bfloat162float(h));
    } else {
        size_t j = i - 2 * CC;
        v = wt[j]; h = __float2bfloat16(v);
        g_wth[j] = h; g_wtl[j] = __float2bfloat16(v - __bfloat162float(h));
    }
}

// ---------------- q/k projection GEMM ----------------
__global__ __launch_bounds__(256, 1)
void mm_qk(const float* __restrict__ bq, const float* __restrict__ bk) {
    int z = blockIdx.z, b = z & 3;
    bool isQ = z < B_;
    const __nv_bfloat16* Ah = (isQ ? g_xh_t : g_xh_r) + (size_t)b * LP_ * C_;
    const __nv_bfloat16* Al = (isQ ? g_xl_t : g_xl_r) + (size_t)b * LP_ * C_;
    const __nv_bfloat16* Bh = isQ ? g_wqh : g_wkh;
    const __nv_bfloat16* Bl = isQ ? g_wql : g_wkl;
    const float* bias = isQ ? bq : bk;
    float* Out = (isQ ? g_qf : g_kf) + (size_t)b * L_ * C_;
    int m0 = blockIdx.y * 128, n0 = blockIdx.x * 128;
    float acc[4][4][4];
    gemm_main(Ah + (size_t)m0 * C_, Al + (size_t)m0 * C_,
              Bh + (size_t)n0 * C_, Bl + (size_t)n0 * C_,
              Bh, Bl, C_, C_, 64, 64, acc);
    int lane = threadIdx.x & 31, warp = threadIdx.x >> 5;
    int wm = (warp >> 2) * 64, wn = (warp & 3) * 32;
#pragma unroll
    for (int mi = 0; mi < 4; mi++)
#pragma unroll
        for (int h = 0; h < 2; h++) {
            int m = m0 + wm + mi * 16 + (lane >> 2) + h * 8;
            if (m >= L_) continue;
#pragma unroll
            for (int nj = 0; nj < 4; nj++) {
                int n = n0 + wn + nj * 8 + (lane & 3) * 2;
                float2 v;
                v.x = acc[mi][nj][2 * h]     + bias[n];
                v.y = acc[mi][nj][2 * h + 1] + bias[n + 1];
                *(float2*)&Out[(size_t)m * C_ + n] = v;
            }
        }
}

// ---------------- split q/k to bf16 (padded rows) + pixel sq-norms ----------------
__global__ void split_qk() {
    int wr = blockIdx.x * 8 + (threadIdx.x >> 5);
    if (wr >= 2 * B_ * LP_) return;
    int lane = threadIdx.x & 31;
    int isK = wr >= B_ * LP_;
    int r = isK ? wr - B_ * LP_ : wr;
    int b = r / LP_, l = r % LP_;
    __nv_bfloat16* oh = (isK ? g_kh : g_qh) + (size_t)r * C_;
    __nv_bfloat16* ol = (isK ? g_kl : g_ql) + (size_t)r * C_;
    if (l >= L_) {
        __nv_bfloat16 z = __float2bfloat16(0.f);
        for (int c = lane; c < C_; c += 32) { oh[c] = z; ol[c] = z; }
        return;
    }
    const float* row = (isK ? g_kf : g_qf) + ((size_t)b * L_ + l) * C_;
    float s = 0.f;
    for (int c = lane; c < C_; c += 32) {
        float v = row[c];
        s += v * v;
        __nv_bfloat16 h = __float2bfloat16(v);
        oh[c] = h;
        ol[c] = __float2bfloat16(v - __bfloat162float(h));
    }
#pragma unroll
    for (int o = 16; o > 0; o >>= 1) s += __shfl_down_sync(0xffffffffu, s, o);
    if (lane == 0) (isK ? g_nk : g_nq)[b * L_ + l] = s;
}

// ---------------- 3x3 box-sum -> inverse patch norms ----------------
__global__ void patchnorm2() {
    int idx = blockIdx.x * blockDim.x + threadIdx.x;
    if (idx >= 2 * B_ * L_) return;
    const float* n = (idx < B_ * L_) ? g_nq : g_nk;
    float* inv = (idx < B_ * L_) ? g_inq : g_ink;
    int id = (idx < B_ * L_) ? idx : idx - B_ * L_;
    int b = id / L_, l = id % L_;
    int li = l / W_, lj = l % W_;
    float s = 0.f;
#pragma unroll
    for (int oi = -1; oi <= 1; oi++)
#pragma unroll
        for (int oj = -1; oj <= 1; oj++) {
            int a = li + oi, c = lj + oj;
            if ((unsigned)a < H_ && (unsigned)c < W_) s += n[b * L_ + a * W_ + c];
        }
    inv[id] = 1.f / fmaxf(sqrtf(s), 1e-12f);
}

// ---------------- Gram GEMM: G[b][m][l] = q[m] . k[l] ----------------
__global__ __launch_bounds__(256, 1)
void mm_gram() {
    int b = blockIdx.z;
    const __nv_bfloat16* Ah = g_qh + (size_t)b * LP_ * C_;
    const __nv_bfloat16* Al = g_ql + (size_t)b * LP_ * C_;
    const __nv_bfloat16* Bh = g_kh + (size_t)b * LP_ * C_;
    const __nv_bfloat16* Bl = g_kl + (size_t)b * LP_ * C_;
    float* Out = g_G + (size_t)b * L_ * L_;
    int m0 = blockIdx.y * 128, n0 = blockIdx.x * 128;
    float acc[4][4][4];
    gemm_main(Ah + (size_t)m0 * C_, Al + (size_t)m0 * C_,
              Bh + (size_t)n0 * C_, Bl + (size_t)n0 * C_,
              Bh, Bl, C_, C_, 64, 64, acc);
    int lane = threadIdx.x & 31, warp = threadIdx.x >> 5;
    int wm = (warp >> 2) * 64, wn = (warp & 3) * 32;
#pragma unroll
    for (int mi = 0; mi < 4; mi++)
#pragma unroll
        for (int h = 0; h < 2; h++) {
            int m = m0 + wm + mi * 16 + (lane >> 2) + h * 8;
            if (m >= L_) continue;
#pragma unroll
            for (int nj = 0; nj < 4; nj++) {
                int n = n0 + wn + nj * 8 + (lane & 3) * 2;
                if (n >= L_) continue;
                float2 v;
                v.x = acc[mi][nj][2 * h];
                v.y = acc[mi][nj][2 * h + 1];
                *(float2*)&Out[(size_t)m * L_ + n] = v;
            }
        }
}

// ---------------- stencil + argmax over l per m ----------------
__global__ void argmax_kernel() {
    int b = blockIdx.y, m = blockIdx.x;
    const float* Gb = g_G + (size_t)b * L_ * L_;
    int mi = m / W_, mj = m % W_;
    float invq = g_inq[b * L_ + m];
    float best = -1e30f;
    int bi = 1 << 30;
    int tid = threadIdx.x;
    for (int l = tid; l < L_; l += 256) {
        int li = l / W_, lj = l % W_;
        float P = 0.f;
#pragma unroll
        for (int oi = -1; oi <= 1; oi++)
#pragma unroll
            for (int oj = -1; oj <= 1; oj++) {
                int a = li + oi, c = lj + oj, d = mi + oi, e = mj + oj;
                if ((unsigned)a < H_ && (unsigned)c < W_ &&
                    (unsigned)d < H_ && (unsigned)e < W_)
                    P += Gb[(size_t)(d * W_ + e) * L_ + (a * W_ + c)];
            }
        float Rv = P * g_ink[b * L_ + l] * invq;
        if (Rv > best) { best = Rv; bi = l; }
    }
    __shared__ float sb[256];
    __shared__ int si[256];
    sb[tid] = best; si[tid] = bi;
    __syncthreads();
    for (int s = 128; s > 0; s >>= 1) {
        if (tid < s) {
            if (sb[tid + s] > sb[tid] ||
                (sb[tid + s] == sb[tid] && si[tid + s] < si[tid])) {
                sb[tid] = sb[tid + s]; si[tid] = si[tid + s];
            }
        }
        __syncthreads();
    }
    if (tid == 0) { g_S[b * L_ + m] = sb[0]; g_arg[b * L_ + m] = si[0]; }
}

// ---------------- fold gather indices ----------------
__global__ void srcidx_kernel() {
    int idx = blockIdx.x * blockDim.x + threadIdx.x;
    if (idx >= B_ * L_) return;
    int b = idx / L_, y = idx % L_;
    int yi = y / W_, yj = y % W_;
#pragma unroll
    for (int di = -1; di <= 1; di++)
#pragma unroll
        for (int dj = -1; dj <= 1; dj++) {
            int jj = (di + 1) * 3 + (dj + 1);
            int s = -1;
            int mi = yi + di, mj = yj + dj;
            if ((unsigned)mi < H_ && (unsigned)mj < W_) {
                int ls = g_arg[b * L_ + mi * W_ + mj];
                int si = ls / W_ - di, sj = ls % W_ - dj;
                if ((unsigned)si < H_ && (unsigned)sj < W_) s = si * W_ + sj;
            }
            g_src[idx * 9 + jj] = s;
        }
}

// ---------------- T_part gather -> bf16 split (padded rows) ----------------
__global__ void gather_kernel() {
    int b = blockIdx.y, y = blockIdx.x;
    __nv_bfloat16* oh = g_Th + ((size_t)b * LP_ + y) * C_;
    __nv_bfloat16* ol = g_Tl + ((size_t)b * LP_ + y) * C_;
    if (y >= L_) {
        __nv_bfloat16 z = __float2bfloat16(0.f);
        for (int c = threadIdx.x; c < C_; c += 256) { oh[c] = z; ol[c] = z; }
        return;
    }
    int s[9];
#pragma unroll
    for (int j = 0; j < 9; j++) s[j] = g_src[((size_t)b * L_ + y) * 9 + j];
    const float* kb = g_kf + (size_t)b * L_ * C_;
    for (int c = threadIdx.x; c < C_; c += 256) {
        float a = 0.f;
#pragma unroll
        for (int j = 0; j < 9; j++)
            if (s[j] >= 0) a += kb[(size_t)s[j] * C_ + c];
        a *= (1.f / 9.f);
        __nv_bfloat16 h = __float2bfloat16(a);
        oh[c] = h;
        ol[c] = __float2bfloat16(a - __bfloat162float(h));
    }
}

// ---------------- final conv: out = (wt.[q;T] + bt)*S + ptgt ----------------
__global__ __launch_bounds__(256, 1)
void mm_final(const float* __restrict__ bt, const float* __restrict__ ptgt,
              float* __restrict__ Out) {
    int b = blockIdx.z;
    const __nv_bfloat16* Bh  = g_qh + (size_t)b * LP_ * C_;
    const __nv_bfloat16* Bl  = g_ql + (size_t)b * LP_ * C_;
    const __nv_bfloat16* Bh2 = g_Th + (size_t)b * LP_ * C_;
    const __nv_bfloat16* Bl2 = g_Tl + (size_t)b * LP_ * C_;
    int m0 = blockIdx.y * 128, n0 = blockIdx.x * 128;
    float acc[4][4][4];
    gemm_main(g_wth + (size_t)m0 * K2C_, g_wtl + (size_t)m0 * K2C_,
              Bh + (size_t)n0 * C_, Bl + (size_t)n0 * C_,
              Bh2 + (size_t)n0 * C_, Bl2 + (size_t)n0 * C_,
              K2C_, C_, 128, 64, acc);
    int lane = threadIdx.x & 31, warp = threadIdx.x >> 5;
    int wm = (warp >> 2) * 64, wn = (warp & 3) * 32;
#pragma unroll
    for (int mi = 0; mi < 4; mi++)
#pragma unroll
        for (int h = 0; h < 2; h++) {
            int m = m0 + wm + mi * 16 + (lane >> 2) + h * 8;
            float bias = bt[m];
#pragma unroll
            for (int nj = 0; nj < 4; nj++) {
                int n = n0 + wn + nj * 8 + (lane & 3) * 2;
                if (n >= L_) continue;
                size_t o = ((size_t)b * C_ + m) * L_ + n;
                float2 v;
                v.x = (acc[mi][nj][2 * h]     + bias) * g_S[b * L_ + n]     + ptgt[o];
                v.y = (acc[mi][nj][2 * h + 1] + bias) * g_S[b * L_ + n + 1] + ptgt[o + 1];
                *(float2*)&Out[o] = v;
            }
        }
}

// ---------------- launch ----------------
extern "C" void kernel_launch(void* const* d_in, const int* in_sizes, int n_in,
                              void* d_out, int out_size) {
    const float* part_ref = (const float*)d_in[0];
    const float* part_tgt = (const float*)d_in[1];
    const float* wq = (const float*)d_in[2];
    const float* bq = (const float*)d_in[3];
    const float* wk = (const float*)d_in[4];
    const float* bk = (const float*)d_in[5];
    const float* wt = (const float*)d_in[6];
    const float* bt = (const float*)d_in[7];
    float* out = (float*)d_out;

    cudaFuncSetAttribute(mm_qk,    cudaFuncAttributeMaxDynamicSharedMemorySize, 2 * STG);
    cudaFuncSetAttribute(mm_gram,  cudaFuncAttributeMaxDynamicSharedMemorySize, 2 * STG);
    cudaFuncSetAttribute(mm_final, cudaFuncAttributeMaxDynamicSharedMemorySize, 2 * STG);

    float *xh_t, *xl_t, *xh_r, *xl_r;
    cudaGetSymbolAddress((void**)&xh_t, g_xh_t);
    cudaGetSymbolAddress((void**)&xl_t, g_xl_t);
    cudaGetSymbolAddress((void**)&xh_r, g_xh_r);
    cudaGetSymbolAddress((void**)&xl_r, g_xl_r);

    dim3 tb(32, 8);
    dim3 tg(LP_ / 32, C_ / 32, B_);
    prep_split<<<tg, tb>>>(part_tgt, (__nv_bfloat16*)xh_t, (__nv_bfloat16*)xl_t);
    prep_split<<<tg, tb>>>(part_ref, (__nv_bfloat16*)xh_r, (__nv_bfloat16*)xl_r);

    size_t wtot = 2 * (size_t)C_ * C_ + (size_t)C_ * K2C_;
    split_w<<<(unsigned)(wtot / 256), 256>>>(wq, wk, wt);

    mm_qk<<<dim3(C_ / 128, LP_ / 128, 2 * B_), 256, 2 * STG>>>(bq, bk);

    split_qk<<<(2 * B_ * LP_ + 7) / 8, 256>>>();
    patchnorm2<<<(2 * B_ * L_ + 255) / 256, 256>>>();

    mm_gram<<<dim3(LP_ / 128, LP_ / 128, B_), 256, 2 * STG>>>();

    argmax_kernel<<<dim3(L_, B_), 256>>>();
    srcidx_kernel<<<(B_ * L_ + 255) / 256, 256>>>();
    gather_kernel<<<dim3(LP_, B_), 256>>>();

    mm_final<<<dim3(LP_ / 128, C_ / 128, B_), 256, 2 * STG>>>(bt, part_tgt, out);
}

// round 9
// speedup vs baseline: 2.5785x; 1.1449x over previous
#include <cuda_runtime.h>
#include <cuda_bf16.h>
#include <math.h>
#include <stdint.h>

#define B_ 4
#define C_ 2048
#define H_ 24
#define W_ 24
#define L_ 576
#define LP_ 640
#define K2C_ 4096

// ---------------- scratch device globals ----------------
__device__ __nv_bfloat16 g_xh_t[B_*LP_*C_], g_xl_t[B_*LP_*C_];
__device__ __nv_bfloat16 g_xh_r[B_*LP_*C_], g_xl_r[B_*LP_*C_];
__device__ __nv_bfloat16 g_wqh[C_*C_], g_wql[C_*C_], g_wkh[C_*C_], g_wkl[C_*C_];
__device__ __nv_bfloat16 g_wth[C_*K2C_], g_wtl[C_*K2C_];
__device__ float g_qf[B_*L_*C_], g_kf[B_*L_*C_];
__device__ __nv_bfloat16 g_qh[B_*LP_*C_], g_ql[B_*LP_*C_];
__device__ __nv_bfloat16 g_kh[B_*LP_*C_], g_kl[B_*LP_*C_];
__device__ __nv_bfloat16 g_Th[B_*LP_*C_], g_Tl[B_*LP_*C_];
__device__ float g_G[B_*L_*L_];
__device__ float g_nq[B_*L_], g_nk[B_*L_], g_inq[B_*L_], g_ink[B_*L_], g_S[B_*L_];
__device__ int g_arg[B_*L_], g_src[B_*L_*9];

// ---------------- PTX helpers ----------------
__device__ __forceinline__ uint32_t smem_u32(const void* p) {
    uint32_t a;
    asm("{ .reg .u64 t; cvta.to.shared.u64 t, %1; cvt.u32.u64 %0, t; }" : "=r"(a) : "l"(p));
    return a;
}
#define CP16(d, s) asm volatile("cp.async.cg.shared.global [%0], [%1], 16;" :: "r"(d), "l"(s))
#define CPCOMMIT() asm volatile("cp.async.commit_group;" ::: "memory")
#define CPWAIT1()  asm volatile("cp.async.wait_group 1;" ::: "memory")
#define CPWAIT0()  asm volatile("cp.async.wait_group 0;" ::: "memory")
__device__ __forceinline__ void ldsm4(uint32_t* r, uint32_t a) {
    asm volatile("ldmatrix.sync.aligned.m8n8.x4.shared.b16 {%0,%1,%2,%3}, [%4];"
                 : "=r"(r[0]), "=r"(r[1]), "=r"(r[2]), "=r"(r[3]) : "r"(a));
}
__device__ __forceinline__ void mma16816(float* d, const uint32_t* a, const uint32_t* b) {
    asm volatile("mma.sync.aligned.m16n8k16.row.col.f32.bf16.bf16.f32 "
                 "{%0,%1,%2,%3},{%4,%5,%6,%7},{%8,%9},{%0,%1,%2,%3};"
                 : "+f"(d[0]), "+f"(d[1]), "+f"(d[2]), "+f"(d[3])
                 : "r"(a[0]), "r"(a[1]), "r"(a[2]), "r"(a[3]), "r"(b[0]), "r"(b[1]));
}

// ---------------- GEMM core: BM=BN=128, BK=32, 8 warps (2x4), warp tile 64x32 ----
// smem tile: [128 rows][32 bf16], pitch 80 bytes -> conflict-free ldmatrix.
// Tiles per stage: [Ah][Bh][Bl](+[Al] if ALO). Passes: AhBh + AhBl (+ AlBh if ALO).
#define TSZ 10240

__device__ __forceinline__ void cpa_tile(uint32_t sb, const __nv_bfloat16* g, int ld, int tid) {
#pragma unroll
    for (int i = 0; i < 2; i++) {
        int idx = tid + i * 256;
        int r = idx >> 2, c = idx & 3;
        CP16(sb + r * 80 + c * 16, g + (size_t)r * ld + c * 8);
    }
}

template<bool ALO>
__device__ void gemm_main(const __nv_bfloat16* Ah, const __nv_bfloat16* Al,
                          const __nv_bfloat16* Bh, const __nv_bfloat16* Bl,
                          const __nv_bfloat16* Bh2, const __nv_bfloat16* Bl2,
                          int lda, int ldb, int KT, int ksw, float acc[4][4][4]) {
    const uint32_t STGSZ = (ALO ? 4 : 3) * TSZ;
    extern __shared__ char smem_[];
    uint32_t sb = smem_u32(smem_);
    int tid = threadIdx.x, lane = tid & 31, warp = tid >> 5;
    int wm = (warp >> 2) * 64, wn = (warp & 3) * 32;
#pragma unroll
    for (int i = 0; i < 4; i++)
#pragma unroll
        for (int j = 0; j < 4; j++)
#pragma unroll
            for (int r = 0; r < 4; r++) acc[i][j][r] = 0.f;

    int rsel = lane & 7, msel = (lane >> 3) & 1, ksel = lane >> 4;

    {
        cpa_tile(sb,           Ah, lda, tid);
        cpa_tile(sb + TSZ,     Bh, ldb, tid);
        cpa_tile(sb + 2 * TSZ, Bl, ldb, tid);
        if (ALO) cpa_tile(sb + 3 * TSZ, Al, lda, tid);
        CPCOMMIT();
    }
    for (int kt = 0; kt < KT; kt++) {
        int cur = kt & 1;
        if (kt + 1 < KT) {
            int k2 = kt + 1;
            uint32_t b0 = sb + (cur ^ 1) * STGSZ;
            const __nv_bfloat16* bh = (k2 < ksw) ? Bh + (size_t)k2 * 32 : Bh2 + (size_t)(k2 - ksw) * 32;
            const __nv_bfloat16* bl = (k2 < ksw) ? Bl + (size_t)k2 * 32 : Bl2 + (size_t)(k2 - ksw) * 32;
            cpa_tile(b0,           Ah + (size_t)k2 * 32, lda, tid);
            cpa_tile(b0 + TSZ,     bh,                   ldb, tid);
            cpa_tile(b0 + 2 * TSZ, bl,                   ldb, tid);
            if (ALO) cpa_tile(b0 + 3 * TSZ, Al + (size_t)k2 * 32, lda, tid);
            CPCOMMIT();
            CPWAIT1();
        } else {
            CPWAIT0();
        }
        __syncthreads();
        uint32_t b0 = sb + cur * STGSZ;
#pragma unroll
        for (int ki = 0; ki < 2; ki++) {
            uint32_t a[4][4], al[4][4], bb[2][4], bl[2][4];
#pragma unroll
            for (int mi = 0; mi < 4; mi++) {
                uint32_t ad = (uint32_t)(wm + mi * 16 + rsel + msel * 8) * 80 + ki * 32 + ksel * 16;
                ldsm4(a[mi], b0 + ad);
                if (ALO) ldsm4(al[mi], b0 + 3 * TSZ + ad);
            }
#pragma unroll
            for (int n2 = 0; n2 < 2; n2++) {
                uint32_t bd = (uint32_t)(wn + n2 * 16 + rsel + msel * 8) * 80 + ki * 32 + ksel * 16;
                ldsm4(bb[n2], b0 + TSZ + bd);
                ldsm4(bl[n2], b0 + 2 * TSZ + bd);
            }
#pragma unroll
            for (int mi = 0; mi < 4; mi++)
#pragma unroll
                for (int nj = 0; nj < 4; nj++) {
                    uint32_t bf[2]  = { bb[nj >> 1][nj & 1], bb[nj >> 1][(nj & 1) + 2] };
                    uint32_t bfl[2] = { bl[nj >> 1][nj & 1], bl[nj >> 1][(nj & 1) + 2] };
                    mma16816(acc[mi][nj], a[mi], bf);
                    mma16816(acc[mi][nj], a[mi], bfl);
                    if (ALO) mma16816(acc[mi][nj], al[mi], bf);
                }
        }
        __syncthreads();
    }
}

// ---------------- prep: transpose [b][c][l] -> [b][l pad 640][c], bf16 split ------
__global__ void prep_split(const float* __restrict__ in,
                           __nv_bfloat16* __restrict__ oh, __nv_bfloat16* __restrict__ ol) {
    __shared__ float t[32][33];
    int b = blockIdx.z;
    int l0 = blockIdx.x * 32, c0 = blockIdx.y * 32;
    int tx = threadIdx.x, ty = threadIdx.y;
#pragma unroll
    for (int j = 0; j < 32; j += 8) {
        int l = l0 + tx;
        t[ty + j][tx] = (l < L_) ? in[((size_t)b * C_ + c0 + ty + j) * L_ + l] : 0.f;
    }
    __syncthreads();
#pragma unroll
    for (int j = 0; j < 32; j += 8) {
        int l = l0 + ty + j, c = c0 + tx;
        float v = t[tx][ty + j];
        __nv_bfloat16 h = __float2bfloat16(v);
        size_t o = ((size_t)b * LP_ + l) * C_ + c;
        oh[o] = h;
        ol[o] = __float2bfloat16(v - __bfloat162float(h));
    }
}

// ---------------- weight splits ----------------
__global__ void split_w(const float* __restrict__ wq, const float* __restrict__ wk,
                        const float* __restrict__ wt) {
    size_t i = (size_t)blockIdx.x * 256 + threadIdx.x;
    const size_t CC = (size_t)C_ * C_;
    float v; __nv_bfloat16 h;
    if (i < CC) {
        v = wq[i]; h = __float2bfloat16(v);
        g_wqh[i] = h; g_wql[i] = __float2bfloat16(v - __bfloat162float(h));
    } else if (i < 2 * CC) {
        size_t j = i - CC;
        v = wk[j]; h = __float2bfloat16(v);
        g_wkh[j] = h; g_wkl[j] = __float2bfloat16(v - __bfloat162float(h));
    } else {
        size_t j = i - 2 * CC;
        v = wt[j]; h = __float2bfloat16(v);
        g_wth[j] = h; g_wtl[j] = __float2bfloat16(v - __bfloat162float(h));
    }
}

// ---------------- q/k projection GEMM (3-pass: feeds argmax) ----------------
__global__ __launch_bounds__(256, 2)
void mm_qk(const float* __restrict__ bq, const float* __restrict__ bk) {
    int z = blockIdx.z, b = z & 3;
    bool isQ = z < B_;
    const __nv_bfloat16* Ah = (isQ ? g_xh_t : g_xh_r) + (size_t)b * LP_ * C_;
    const __nv_bfloat16* Al = (isQ ? g_xl_t : g_xl_r) + (size_t)b * LP_ * C_;
    const __nv_bfloat16* Bh = isQ ? g_wqh : g_wkh;
    const __nv_bfloat16* Bl = isQ ? g_wql : g_wkl;
    const float* bias = isQ ? bq : bk;
    float* Out = (isQ ? g_qf : g_kf) + (size_t)b * L_ * C_;
    int m0 = blockIdx.y * 128, n0 = blockIdx.x * 128;
    float acc[4][4][4];
    gemm_main<true>(Ah + (size_t)m0 * C_, Al + (size_t)m0 * C_,
                    Bh + (size_t)n0 * C_, Bl + (size_t)n0 * C_,
                    Bh, Bl, C_, C_, 64, 64, acc);
    int lane = threadIdx.x & 31, warp = threadIdx.x >> 5;
    int wm = (warp >> 2) * 64, wn = (warp & 3) * 32;
#pragma unroll
    for (int mi = 0; mi < 4; mi++)
#pragma unroll
        for (int h = 0; h < 2; h++) {
            int m = m0 + wm + mi * 16 + (lane >> 2) + h * 8;
            if (m >= L_) continue;
#pragma unroll
            for (int nj = 0; nj < 4; nj++) {
                int n = n0 + wn + nj * 8 + (lane & 3) * 2;
                float2 v;
                v.x = acc[mi][nj][2 * h]     + bias[n];
                v.y = acc[mi][nj][2 * h + 1] + bias[n + 1];
                *(float2*)&Out[(size_t)m * C_ + n] = v;
            }
        }
}

// ---------------- split q/k to bf16 (padded rows) + pixel sq-norms ----------------
__global__ void split_qk() {
    int wr = blockIdx.x * 8 + (threadIdx.x >> 5);
    if (wr >= 2 * B_ * LP_) return;
    int lane = threadIdx.x & 31;
    int isK = wr >= B_ * LP_;
    int r = isK ? wr - B_ * LP_ : wr;
    int b = r / LP_, l = r % LP_;
    __nv_bfloat16* oh = (isK ? g_kh : g_qh) + (size_t)r * C_;
    __nv_bfloat16* ol = (isK ? g_kl : g_ql) + (size_t)r * C_;
    if (l >= L_) {
        __nv_bfloat16 z = __float2bfloat16(0.f);
        for (int c = lane; c < C_; c += 32) { oh[c] = z; ol[c] = z; }
        return;
    }
    const float* row = (isK ? g_kf : g_qf) + ((size_t)b * L_ + l) * C_;
    float s = 0.f;
    for (int c = lane; c < C_; c += 32) {
        float v = row[c];
        s += v * v;
        __nv_bfloat16 h = __float2bfloat16(v);
        oh[c] = h;
        ol[c] = __float2bfloat16(v - __bfloat162float(h));
    }
#pragma unroll
    for (int o = 16; o > 0; o >>= 1) s += __shfl_down_sync(0xffffffffu, s, o);
    if (lane == 0) (isK ? g_nk : g_nq)[b * L_ + l] = s;
}

// ---------------- 3x3 box-sum -> inverse patch norms ----------------
__global__ void patchnorm2() {
    int idx = blockIdx.x * blockDim.x + threadIdx.x;
    if (idx >= 2 * B_ * L_) return;
    const float* n = (idx < B_ * L_) ? g_nq : g_nk;
    float* inv = (idx < B_ * L_) ? g_inq : g_ink;
    int id = (idx < B_ * L_) ? idx : idx - B_ * L_;
    int b = id / L_, l = id % L_;
    int li = l / W_, lj = l % W_;
    float s = 0.f;
#pragma unroll
    for (int oi = -1; oi <= 1; oi++)
#pragma unroll
        for (int oj = -1; oj <= 1; oj++) {
            int a = li + oi, c = lj + oj;
            if ((unsigned)a < H_ && (unsigned)c < W_) s += n[b * L_ + a * W_ + c];
        }
    inv[id] = 1.f / fmaxf(sqrtf(s), 1e-12f);
}

// ---------------- Gram GEMM: G[b][m][l] = q[m] . k[l]  (3-pass: feeds argmax) ----
__global__ __launch_bounds__(256, 2)
void mm_gram() {
    int b = blockIdx.z;
    const __nv_bfloat16* Ah = g_qh + (size_t)b * LP_ * C_;
    const __nv_bfloat16* Al = g_ql + (size_t)b * LP_ * C_;
    const __nv_bfloat16* Bh = g_kh + (size_t)b * LP_ * C_;
    const __nv_bfloat16* Bl = g_kl + (size_t)b * LP_ * C_;
    float* Out = g_G + (size_t)b * L_ * L_;
    int m0 = blockIdx.y * 128, n0 = blockIdx.x * 128;
    float acc[4][4][4];
    gemm_main<true>(Ah + (size_t)m0 * C_, Al + (size_t)m0 * C_,
                    Bh + (size_t)n0 * C_, Bl + (size_t)n0 * C_,
                    Bh, Bl, C_, C_, 64, 64, acc);
    int lane = threadIdx.x & 31, warp = threadIdx.x >> 5;
    int wm = (warp >> 2) * 64, wn = (warp & 3) * 32;
#pragma unroll
    for (int mi = 0; mi < 4; mi++)
#pragma unroll
        for (int h = 0; h < 2; h++) {
            int m = m0 + wm + mi * 16 + (lane >> 2) + h * 8;
            if (m >= L_) continue;
#pragma unroll
            for (int nj = 0; nj < 4; nj++) {
                int n = n0 + wn + nj * 8 + (lane & 3) * 2;
                if (n >= L_) continue;
                float2 v;
                v.x = acc[mi][nj][2 * h];
                v.y = acc[mi][nj][2 * h + 1];
                *(float2*)&Out[(size_t)m * L_ + n] = v;
            }
        }
}

// ---------------- stencil + argmax over l per m ----------------
__global__ void argmax_kernel() {
    int b = blockIdx.y, m = blockIdx.x;
    const float* Gb = g_G + (size_t)b * L_ * L_;
    int mi = m / W_, mj = m % W_;
    float invq = g_inq[b * L_ + m];
    float best = -1e30f;
    int bi = 1 << 30;
    int tid = threadIdx.x;
    for (int l = tid; l < L_; l += 256) {
        int li = l / W_, lj = l % W_;
        float P = 0.f;
#pragma unroll
        for (int oi = -1; oi <= 1; oi++)
#pragma unroll
            for (int oj = -1; oj <= 1; oj++) {
                int a = li + oi, c = lj + oj, d = mi + oi, e = mj + oj;
                if ((unsigned)a < H_ && (unsigned)c < W_ &&
                    (unsigned)d < H_ && (unsigned)e < W_)
                    P += Gb[(size_t)(d * W_ + e) * L_ + (a * W_ + c)];
            }
        float Rv = P * g_ink[b * L_ + l] * invq;
        if (Rv > best) { best = Rv; bi = l; }
    }
    __shared__ float sb[256];
    __shared__ int si[256];
    sb[tid] = best; si[tid] = bi;
    __syncthreads();
    for (int s = 128; s > 0; s >>= 1) {
        if (tid < s) {
            if (sb[tid + s] > sb[tid] ||
                (sb[tid + s] == sb[tid] && si[tid + s] < si[tid])) {
                sb[tid] = sb[tid + s]; si[tid] = si[tid + s];
            }
        }
        __syncthreads();
    }
    if (tid == 0) { g_S[b * L_ + m] = sb[0]; g_arg[b * L_ + m] = si[0]; }
}

// ---------------- fold gather indices ----------------
__global__ void srcidx_kernel() {
    int idx = blockIdx.x * blockDim.x + threadIdx.x;
    if (idx >= B_ * L_) return;
    int b = idx / L_, y = idx % L_;
    int yi = y / W_, yj = y % W_;
#pragma unroll
    for (int di = -1; di <= 1; di++)
#pragma unroll
        for (int dj = -1; dj <= 1; dj++) {
            int jj = (di + 1) * 3 + (dj + 1);
            int s = -1;
            int mi = yi + di, mj = yj + dj;
            if ((unsigned)mi < H_ && (unsigned)mj < W_) {
                int ls = g_arg[b * L_ + mi * W_ + mj];
                int si = ls / W_ - di, sj = ls % W_ - dj;
                if ((unsigned)si < H_ && (unsigned)sj < W_) s = si * W_ + sj;
            }
            g_src[idx * 9 + jj] = s;
        }
}

// ---------------- T_part gather -> bf16 split (padded rows) ----------------
__global__ void gather_kernel() {
    int b = blockIdx.y, y = blockIdx.x;
    __nv_bfloat16* oh = g_Th + ((size_t)b * LP_ + y) * C_;
    __nv_bfloat16* ol = g_Tl + ((size_t)b * LP_ + y) * C_;
    if (y >= L_) {
        __nv_bfloat16 z = __float2bfloat16(0.f);
        for (int c = threadIdx.x; c < C_; c += 256) { oh[c] = z; ol[c] = z; }
        return;
    }
    int s[9];
#pragma unroll
    for (int j = 0; j < 9; j++) s[j] = g_src[((size_t)b * L_ + y) * 9 + j];
    const float* kb = g_kf + (size_t)b * L_ * C_;
    for (int c = threadIdx.x; c < C_; c += 256) {
        float a = 0.f;
#pragma unroll
        for (int j = 0; j < 9; j++)
            if (s[j] >= 0) a += kb[(size_t)s[j] * C_ + c];
        a *= (1.f / 9.f);
        __nv_bfloat16 h = __float2bfloat16(a);
        oh[c] = h;
        ol[c] = __float2bfloat16(a - __bfloat162float(h));
    }
}

// ---------------- final conv (2-pass: downstream of argmax) ----------------
__global__ __launch_bounds__(256, 2)
void mm_final(const float* __restrict__ bt, const float* __restrict__ ptgt,
              float* __restrict__ Out) {
    int b = blockIdx.z;
    const __nv_bfloat16* Bh  = g_qh + (size_t)b * LP_ * C_;
    const __nv_bfloat16* Bl  = g_ql + (size_t)b * LP_ * C_;
    const __nv_bfloat16* Bh2 = g_Th + (size_t)b * LP_ * C_;
    const __nv_bfloat16* Bl2 = g_Tl + (size_t)b * LP_ * C_;
    int m0 = blockIdx.y * 128, n0 = blockIdx.x * 128;
    float acc[4][4][4];
    gemm_main<false>(g_wth + (size_t)m0 * K2C_, g_wth,
                     Bh + (size_t)n0 * C_, Bl + (size_t)n0 * C_,
                     Bh2 + (size_t)n0 * C_, Bl2 + (size_t)n0 * C_,
                     K2C_, C_, 128, 64, acc);
    int lane = threadIdx.x & 31, warp = threadIdx.x >> 5;
    int wm = (warp >> 2) * 64, wn = (warp & 3) * 32;
#pragma unroll
    for (int mi = 0; mi < 4; mi++)
#pragma unroll
        for (int h = 0; h < 2; h++) {
            int m = m0 + wm + mi * 16 + (lane >> 2) + h * 8;
            float bias = bt[m];
#pragma unroll
            for (int nj = 0; nj < 4; nj++) {
                int n = n0 + wn + nj * 8 + (lane & 3) * 2;
                if (n >= L_) continue;
                size_t o = ((size_t)b * C_ + m) * L_ + n;
                float2 v;
                v.x = (acc[mi][nj][2 * h]     + bias) * g_S[b * L_ + n]     + ptgt[o];
                v.y = (acc[mi][nj][2 * h + 1] + bias) * g_S[b * L_ + n + 1] + ptgt[o + 1];
                *(float2*)&Out[o] = v;
            }
        }
}

// ---------------- launch ----------------
extern "C" void kernel_launch(void* const* d_in, const int* in_sizes, int n_in,
                              void* d_out, int out_size) {
    const float* part_ref = (const float*)d_in[0];
    const float* part_tgt = (const float*)d_in[1];
    const float* wq = (const float*)d_in[2];
    const float* bq = (const float*)d_in[3];
    const float* wk = (const float*)d_in[4];
    const float* bk = (const float*)d_in[5];
    const float* wt = (const float*)d_in[6];
    const float* bt = (const float*)d_in[7];
    float* out = (float*)d_out;

    const int SMEM4 = 2 * 4 * TSZ;   // qk/gram: 2 stages x 4 tiles
    const int SMEM3 = 2 * 3 * TSZ;   // final:   2 stages x 3 tiles
    cudaFuncSetAttribute(mm_qk,    cudaFuncAttributeMaxDynamicSharedMemorySize, SMEM4);
    cudaFuncSetAttribute(mm_gram,  cudaFuncAttributeMaxDynamicSharedMemorySize, SMEM4);
    cudaFuncSetAttribute(mm_final, cudaFuncAttributeMaxDynamicSharedMemorySize, SMEM3);

    float *xh_t, *xl_t, *xh_r, *xl_r;
    cudaGetSymbolAddress((void**)&xh_t, g_xh_t);
    cudaGetSymbolAddress((void**)&xl_t, g_xl_t);
    cudaGetSymbolAddress((void**)&xh_r, g_xh_r);
    cudaGetSymbolAddress((void**)&xl_r, g_xl_r);

    dim3 tb(32, 8);
    dim3 tg(LP_ / 32, C_ / 32, B_);
    prep_split<<<tg, tb>>>(part_tgt, (__nv_bfloat16*)xh_t, (__nv_bfloat16*)xl_t);
    prep_split<<<tg, tb>>>(part_ref, (__nv_bfloat16*)xh_r, (__nv_bfloat16*)xl_r);

    size_t wtot = 2 * (size_t)C_ * C_ + (size_t)C_ * K2C_;
    split_w<<<(unsigned)(wtot / 256), 256>>>(wq, wk, wt);

    mm_qk<<<dim3(C_ / 128, LP_ / 128, 2 * B_), 256, SMEM4>>>(bq, bk);

    split_qk<<<(2 * B_ * LP_ + 7) / 8, 256>>>();
    patchnorm2<<<(2 * B_ * L_ + 255) / 256, 256>>>();

    mm_gram<<<dim3(LP_ / 128, LP_ / 128, B_), 256, SMEM4>>>();

    argmax_kernel<<<dim3(L_, B_), 256>>>();
    srcidx_kernel<<<(B_ * L_ + 255) / 256, 256>>>();
    gather_kernel<<<dim3(LP_, B_), 256>>>();

    mm_final<<<dim3(LP_ / 128, C_ / 128, B_), 256, SMEM3>>>(bt, part_tgt, out);
}